// round 2
// baseline (speedup 1.0000x reference)
#include <cuda_runtime.h>
#include <math.h>

// L2loss over bucketized histograms.
//   For each channel c in 0..2, for each tensor (target, output):
//     cum = floor(cumsum(hist_c))            (int32, nondecreasing)
//     s(p) = searchsorted(cum, p, 'right')   (count of cum[j] <= p, in [0,256])
//     h(p) = (s == K-1) ? h_prev(p) : min(s, K-1)   -- carry across channels
//   loss = sum_c sqrt( sum_p (h1-h2)^2 )
//
// One kernel launch: 98 blocks x 512 threads = 50176 = one thread per position,
// exactly one wave. Cross-block reduction via u64 atomics + self-resetting
// ticket (graph-replay safe, no extra kernels, no allocations).

namespace {
constexpr int KBINS = 256;
constexpr int NPIX  = 224 * 224;   // 50176
constexpr int TPB   = 512;
constexpr int NBLK  = NPIX / TPB;  // 98
}

__device__ unsigned long long g_acc[3];   // zero-initialized; reset by last block
__device__ unsigned int       g_ticket;   // self-resetting via atomicInc wrap

__global__ void __launch_bounds__(TPB)
l2hist_kernel(const float* __restrict__ target,
              const float* __restrict__ output,
              float* __restrict__ out)
{
    __shared__ float        s_raw[6][KBINS];
    __shared__ int          s_cum[6][KBINS];
    __shared__ unsigned int s_wred[TPB / 32][3];

    const int tid = threadIdx.x;

    // Cooperative coalesced load of all 6 histograms (3 target + 3 output).
    for (int i = tid; i < 6 * KBINS; i += TPB) {
        const int a = i >> 8;          // which array 0..5
        const int j = i & (KBINS - 1); // bin
        s_raw[a][j] = (a < 3) ? target[(a << 8) + j]
                              : output[((a - 3) << 8) + j];
    }
    __syncthreads();

    // Sequential fp32 cumsum per array (matches reference rounding order),
    // floored to int32. 6 threads, 256 iterations each.
    if (tid < 6) {
        float c = 0.0f;
        #pragma unroll 4
        for (int j = 0; j < KBINS; ++j) {
            c += s_raw[tid][j];
            s_cum[tid][j] = (int)floorf(c);
        }
    }
    __syncthreads();

    const int p = blockIdx.x * TPB + tid;   // pixel position, always < NPIX

    // Per-position bucketize with cross-channel carry.
    int h1 = 0, h2 = 0;
    unsigned int acc[3];
    #pragma unroll
    for (int c = 0; c < 3; ++c) {
        // Branchless count of elements <= p (saturates at 255; the 256 case
        // is disambiguated below via the cum[255] compare).
        int s1 = 0, s2 = 0;
        #pragma unroll
        for (int w = 128; w; w >>= 1) {
            if (s_cum[c    ][s1 + w - 1] <= p) s1 += w;
            if (s_cum[c + 3][s2 + w - 1] <= p) s2 += w;
        }
        // True count semantics:
        //   count <  K-1 : h = count
        //   count == K-1 : keep previous channel's value (the "gap")
        //   count == K   : h = K-1           (p >= cum[K-1])
        if (s1 != KBINS - 1)                   h1 = s1;
        else if (s_cum[c    ][KBINS - 1] <= p) h1 = KBINS - 1;  // count was 256
        if (s2 != KBINS - 1)                   h2 = s2;
        else if (s_cum[c + 3][KBINS - 1] <= p) h2 = KBINS - 1;  // count was 256
        const int d = h1 - h2;
        acc[c] = (unsigned int)(d * d);     // <= 255^2, block sum fits u32
    }

    // Warp reduce, then block reduce in shared.
    #pragma unroll
    for (int c = 0; c < 3; ++c) {
        #pragma unroll
        for (int off = 16; off; off >>= 1)
            acc[c] += __shfl_xor_sync(0xFFFFFFFFu, acc[c], off);
    }
    const int lane = tid & 31;
    const int warp = tid >> 5;
    if (lane == 0) {
        s_wred[warp][0] = acc[0];
        s_wred[warp][1] = acc[1];
        s_wred[warp][2] = acc[2];
    }
    __syncthreads();

    if (tid == 0) {
        unsigned long long t0 = 0, t1 = 0, t2 = 0;
        #pragma unroll
        for (int w = 0; w < TPB / 32; ++w) {
            t0 += s_wred[w][0];
            t1 += s_wred[w][1];
            t2 += s_wred[w][2];
        }
        atomicAdd(&g_acc[0], t0);
        atomicAdd(&g_acc[1], t1);
        atomicAdd(&g_acc[2], t2);
        __threadfence();
        // atomicInc with val=NBLK-1 wraps 97 -> 0: self-resetting ticket.
        const unsigned int prev = atomicInc(&g_ticket, NBLK - 1);
        if (prev == NBLK - 1) {
            // Last block: all other blocks' adds are visible
            // (their threadfence happened before their ticket inc).
            __threadfence();
            const unsigned long long a0 = atomicAdd(&g_acc[0], 0ULL);
            const unsigned long long a1 = atomicAdd(&g_acc[1], 0ULL);
            const unsigned long long a2 = atomicAdd(&g_acc[2], 0ULL);
            *out = (float)(sqrt((double)a0) + sqrt((double)a1) + sqrt((double)a2));
            // Reset for the next graph replay.
            g_acc[0] = 0ULL; g_acc[1] = 0ULL; g_acc[2] = 0ULL;
            __threadfence();
        }
    }
}

extern "C" void kernel_launch(void* const* d_in, const int* in_sizes, int n_in,
                              void* d_out, int out_size)
{
    const float* target = (const float*)d_in[0];  // (3, 256, 1) fp32
    const float* output = (const float*)d_in[1];  // (3, 256, 1) fp32
    float* out = (float*)d_out;                   // scalar fp32
    (void)in_sizes; (void)n_in; (void)out_size;

    l2hist_kernel<<<NBLK, TPB>>>(target, output, out);
}

// round 3
// speedup vs baseline: 1.7493x; 1.7493x over previous
#include <cuda_runtime.h>
#include <math.h>

// L2loss over bucketized histograms (see reference):
//   cum = floor(cumsum(hist)) ; s(p) = count(cum <= p) in [0,256]
//   h(p) = (s == K-1) ? h_prev(p) : min(s, K-1)   (carry across channels)
//   loss = sum_c sqrt( sum_p (h1-h2)^2 )
//
// One launch, one wave: 98 blocks x 512 threads = 50176 positions.
// R3: warp-parallel cumsum (6 warps, shfl Kogge-Stone + serial carry) replaces
// the 256-step sequential scan that dominated R2's 18us.

namespace {
constexpr int KBINS = 256;
constexpr int NPIX  = 224 * 224;   // 50176
constexpr int TPB   = 512;
constexpr int NBLK  = NPIX / TPB;  // 98
}

__device__ unsigned long long g_acc[3];   // zero-init; reset by last block
__device__ unsigned int       g_ticket;   // self-resetting via atomicInc wrap

__global__ void __launch_bounds__(TPB)
l2hist_kernel(const float* __restrict__ target,
              const float* __restrict__ output,
              float* __restrict__ out)
{
    __shared__ float        s_raw[6][KBINS];
    __shared__ int          s_cum[6][KBINS];
    __shared__ unsigned int s_wred[TPB / 32][3];

    const int tid  = threadIdx.x;
    const int lane = tid & 31;
    const int warp = tid >> 5;

    // Coalesced load of all 6 histograms (3 target + 3 output), 3 elems/thread.
    #pragma unroll
    for (int i = tid; i < 6 * KBINS; i += TPB) {
        const int a = i >> 8;
        const int j = i & (KBINS - 1);
        s_raw[a][j] = (a < 3) ? target[(a << 8) + j]
                              : output[((a - 3) << 8) + j];
    }
    __syncthreads();

    // Warp-parallel inclusive scan: warp a (a<6) scans array a.
    // 8 segments of 32, shfl Kogge-Stone per segment, serial carry between.
    if (warp < 6) {
        float carry = 0.0f;
        #pragma unroll
        for (int seg = 0; seg < 8; ++seg) {
            float v = s_raw[warp][(seg << 5) + lane];
            #pragma unroll
            for (int off = 1; off < 32; off <<= 1) {
                const float n = __shfl_up_sync(0xFFFFFFFFu, v, off);
                if (lane >= off) v += n;
            }
            const float tot = __shfl_sync(0xFFFFFFFFu, v, 31); // segment total
            v += carry;
            carry += tot;
            s_cum[warp][(seg << 5) + lane] = (int)floorf(v);
        }
    }
    __syncthreads();

    const int p = blockIdx.x * TPB + tid;   // pixel position (< NPIX always)

    // Six independent branchless binary searches (count of cum[j] <= p,
    // saturating at 255; the 256 case disambiguated via cum[255] below).
    int s[6];
    #pragma unroll
    for (int a = 0; a < 6; ++a) s[a] = 0;
    #pragma unroll
    for (int w = 128; w; w >>= 1) {
        #pragma unroll
        for (int a = 0; a < 6; ++a)
            if (s_cum[a][s[a] + w - 1] <= p) s[a] += w;
    }

    // Carry semantics across channels + per-channel squared diff.
    int h1 = 0, h2 = 0;
    unsigned int acc[3];
    #pragma unroll
    for (int c = 0; c < 3; ++c) {
        const int s1 = s[c], s2 = s[c + 3];
        if (s1 != KBINS - 1)                   h1 = s1;
        else if (s_cum[c    ][KBINS - 1] <= p) h1 = KBINS - 1;  // count was 256
        if (s2 != KBINS - 1)                   h2 = s2;
        else if (s_cum[c + 3][KBINS - 1] <= p) h2 = KBINS - 1;  // count was 256
        const int d = h1 - h2;
        acc[c] = (unsigned int)(d * d);     // <= 255^2; block sum fits u32
    }

    // Warp reduce (REDUX) then block reduce.
    #pragma unroll
    for (int c = 0; c < 3; ++c)
        acc[c] = __reduce_add_sync(0xFFFFFFFFu, acc[c]);
    if (lane == 0) {
        s_wred[warp][0] = acc[0];
        s_wred[warp][1] = acc[1];
        s_wred[warp][2] = acc[2];
    }
    __syncthreads();

    if (tid == 0) {
        unsigned long long t0 = 0, t1 = 0, t2 = 0;
        #pragma unroll
        for (int w = 0; w < TPB / 32; ++w) {
            t0 += s_wred[w][0];
            t1 += s_wred[w][1];
            t2 += s_wred[w][2];
        }
        atomicAdd(&g_acc[0], t0);
        atomicAdd(&g_acc[1], t1);
        atomicAdd(&g_acc[2], t2);
        __threadfence();
        // atomicInc with val=NBLK-1 wraps 97 -> 0: self-resetting ticket.
        const unsigned int prev = atomicInc(&g_ticket, NBLK - 1);
        if (prev == NBLK - 1) {
            __threadfence();
            const unsigned long long a0 = atomicAdd(&g_acc[0], 0ULL);
            const unsigned long long a1 = atomicAdd(&g_acc[1], 0ULL);
            const unsigned long long a2 = atomicAdd(&g_acc[2], 0ULL);
            *out = (float)(sqrt((double)a0) + sqrt((double)a1) + sqrt((double)a2));
            g_acc[0] = 0ULL; g_acc[1] = 0ULL; g_acc[2] = 0ULL;  // replay reset
            __threadfence();
        }
    }
}

extern "C" void kernel_launch(void* const* d_in, const int* in_sizes, int n_in,
                              void* d_out, int out_size)
{
    const float* target = (const float*)d_in[0];  // (3, 256, 1) fp32
    const float* output = (const float*)d_in[1];  // (3, 256, 1) fp32
    float* out = (float*)d_out;                   // scalar fp32
    (void)in_sizes; (void)n_in; (void)out_size;

    l2hist_kernel<<<NBLK, TPB>>>(target, output, out);
}

// round 4
// speedup vs baseline: 2.2059x; 1.2610x over previous
#include <cuda_runtime.h>
#include <math.h>

// L2loss over bucketized histograms:
//   cum = floor(cumsum(hist)) ; s(p) = count(cum <= p) in [0,256]
//   h(p) = (s == K-1) ? h_prev(p) : min(s, K-1)   (carry across channels)
//   loss = sum_c sqrt( sum_p (h1-h2)^2 )
//
// R4: 49 blocks x 1024 threads = 50176 = 1 px/thread, one wave.
//  - scan warps load their array directly from global (2x float4/lane),
//    per-lane serial 8-sum + 5-level Kogge-Stone + exclusive via shfl_up(1):
//    ~250cy instead of ~1.3k.
//  - warp-level block reduce (REDUX), packed u64+u32 REDG accumulators,
//    halved ticket chain.

namespace {
constexpr int KBINS = 256;
constexpr int NPIX  = 224 * 224;    // 50176
constexpr int TPB   = 1024;
constexpr int NBLK  = NPIX / TPB;   // 49, exact
constexpr int NWARP = TPB / 32;     // 32
}

__device__ unsigned long long g_acc01;   // ch0 in low 32, ch1 in high 32
__device__ unsigned int       g_acc2;    // ch2
__device__ unsigned int       g_ticket;  // self-resetting via atomicInc wrap

__global__ void __launch_bounds__(TPB)
l2hist_kernel(const float* __restrict__ target,
              const float* __restrict__ output,
              float* __restrict__ out)
{
    __shared__ alignas(16) int s_cum[6][KBINS];
    __shared__ unsigned int    s_wred[NWARP][3];

    const int tid  = threadIdx.x;
    const int lane = tid & 31;
    const int warp = tid >> 5;

    // ---- Scan: warp a (a<6) computes floor(cumsum) of array a. ----
    // Lane l owns elements [8l, 8l+8). Serial in-lane prefix (matches the
    // reference order within the chunk), Kogge-Stone across lane totals.
    if (warp < 6) {
        const float* src = (warp < 3) ? target + (warp << 8)
                                      : output + ((warp - 3) << 8);
        const float4 v0 = __ldg((const float4*)(src + (lane << 3)));
        const float4 v1 = __ldg((const float4*)(src + (lane << 3) + 4));

        float q0 = v0.x;
        float q1 = q0 + v0.y;
        float q2 = q1 + v0.z;
        float q3 = q2 + v0.w;
        float q4 = q3 + v1.x;
        float q5 = q4 + v1.y;
        float q6 = q5 + v1.z;
        float q7 = q6 + v1.w;          // lane total

        float inc = q7;                // inclusive scan of lane totals
        #pragma unroll
        for (int off = 1; off < 32; off <<= 1) {
            const float n = __shfl_up_sync(0xFFFFFFFFu, inc, off);
            if (lane >= off) inc += n;
        }
        float excl = __shfl_up_sync(0xFFFFFFFFu, inc, 1);
        if (lane == 0) excl = 0.0f;

        int4 w0, w1;
        w0.x = __float2int_rd(excl + q0);
        w0.y = __float2int_rd(excl + q1);
        w0.z = __float2int_rd(excl + q2);
        w0.w = __float2int_rd(excl + q3);
        w1.x = __float2int_rd(excl + q4);
        w1.y = __float2int_rd(excl + q5);
        w1.z = __float2int_rd(excl + q6);
        w1.w = __float2int_rd(excl + q7);
        *(int4*)&s_cum[warp][(lane << 3)]     = w0;
        *(int4*)&s_cum[warp][(lane << 3) + 4] = w1;
    }
    __syncthreads();

    const int p = blockIdx.x * TPB + tid;   // pixel position (< NPIX always)

    // ---- Six interleaved branchless binary searches: count(cum[j] <= p),
    //      saturating at 255; the 256 case disambiguated via cum[255]. ----
    int s[6];
    #pragma unroll
    for (int a = 0; a < 6; ++a) s[a] = 0;
    #pragma unroll
    for (int w = 128; w; w >>= 1) {
        #pragma unroll
        for (int a = 0; a < 6; ++a)
            if (s_cum[a][s[a] + w - 1] <= p) s[a] += w;
    }

    // ---- Carry semantics across channels + squared diffs. ----
    int h1 = 0, h2 = 0;
    unsigned int acc[3];
    #pragma unroll
    for (int c = 0; c < 3; ++c) {
        const int s1 = s[c], s2 = s[c + 3];
        if (s1 != KBINS - 1)                   h1 = s1;
        else if (s_cum[c    ][KBINS - 1] <= p) h1 = KBINS - 1;  // count was 256
        if (s2 != KBINS - 1)                   h2 = s2;
        else if (s_cum[c + 3][KBINS - 1] <= p) h2 = KBINS - 1;  // count was 256
        const int d = h1 - h2;
        acc[c] = (unsigned int)(d * d);
    }

    // ---- Warp reduce then warp0 block-reduce. ----
    #pragma unroll
    for (int c = 0; c < 3; ++c)
        acc[c] = __reduce_add_sync(0xFFFFFFFFu, acc[c]);
    if (lane == 0) {
        s_wred[warp][0] = acc[0];
        s_wred[warp][1] = acc[1];
        s_wred[warp][2] = acc[2];
    }
    __syncthreads();

    if (warp == 0) {
        unsigned int b0 = s_wred[lane][0];
        unsigned int b1 = s_wred[lane][1];
        unsigned int b2 = s_wred[lane][2];
        b0 = __reduce_add_sync(0xFFFFFFFFu, b0);
        b1 = __reduce_add_sync(0xFFFFFFFFu, b1);
        b2 = __reduce_add_sync(0xFFFFFFFFu, b2);
        if (lane == 0) {
            // ch sums < 2^32 globally, so packed u64 add has no lane carry.
            atomicAdd(&g_acc01, (unsigned long long)b0 |
                                ((unsigned long long)b1 << 32));
            atomicAdd(&g_acc2, b2);
            __threadfence();
            // atomicInc with val=NBLK-1 wraps 48 -> 0: self-resetting ticket.
            const unsigned int prev = atomicInc(&g_ticket, NBLK - 1);
            if (prev == NBLK - 1) {
                __threadfence();
                const unsigned long long a01 = atomicAdd(&g_acc01, 0ULL);
                const unsigned int       a2  = atomicAdd(&g_acc2, 0u);
                const float r0 = sqrtf((float)(unsigned int)(a01 & 0xFFFFFFFFu));
                const float r1 = sqrtf((float)(unsigned int)(a01 >> 32));
                const float r2 = sqrtf((float)a2);
                *out = r0 + r1 + r2;
                g_acc01 = 0ULL; g_acc2 = 0u;   // replay reset
                __threadfence();
            }
        }
    }
}

extern "C" void kernel_launch(void* const* d_in, const int* in_sizes, int n_in,
                              void* d_out, int out_size)
{
    const float* target = (const float*)d_in[0];  // (3, 256, 1) fp32
    const float* output = (const float*)d_in[1];  // (3, 256, 1) fp32
    float* out = (float*)d_out;                   // scalar fp32
    (void)in_sizes; (void)n_in; (void)out_size;

    l2hist_kernel<<<NBLK, TPB>>>(target, output, out);
}